// round 1
// baseline (speedup 1.0000x reference)
#include <cuda_runtime.h>
#include <math.h>

// Problem shape (fixed by dataset)
#define BB 2
#define CC 16
#define FP 30
#define FA 50
#define SS 20
#define TT 1024
#define NB 18
#define NBC 19            // number of cutoffs = NB+1

#define THREADS 960       // 30 warps; warp w owns p=w
#define TILE_T 128
#define HIST_STRIDE 19    // per-a stride (coprime with 32 -> conflict-free)
#define HIST_P (FA * HIST_STRIDE)   // 950 floats per p
#define NOUT (BB*CC*FP*FA)          // 48000

// SMEM layout (in floats)
#define OFF_HIST 0                        // FP*HIST_P = 28500
#define OFF_CNT  (OFF_HIST + FP*HIST_P)   // 28500, size FP*NB = 540
#define OFF_CUT  (OFF_CNT + FP*NB)        // 29040, size 20
#define OFF_AMP  (OFF_CUT + 20)           // 29060, size TILE_T*FA = 6400
#define OFF_BINS (OFF_AMP + TILE_T*FA)    // 35460, size FP*TT/4 u32 = 7680
#define SMEM_FLOATS (OFF_BINS + FP*TT/4)  // 43140 floats = 172560 bytes

__device__ float g_scratch[SS * NOUT];    // per-s MI values, reduced by stage 2

__global__ __launch_bounds__(THREADS, 1)
void mi_main(const float* __restrict__ pha,
             const float* __restrict__ amp,
             const float* __restrict__ cuts)
{
    extern __shared__ float sm[];
    float*    hist  = sm + OFF_HIST;               // [FP][FA*19]
    float*    cnts  = sm + OFF_CNT;                // [FP][NB]
    float*    cut   = sm + OFF_CUT;                // [NBC]
    float*    amp_s = sm + OFF_AMP;                // [TILE_T][FA]
    unsigned* binsU = (unsigned*)(sm + OFF_BINS);  // [FP][TT/4] packed bytes

    const int tid  = threadIdx.x;
    const int wid  = tid >> 5;
    const int lane = tid & 31;
    const int bid  = blockIdx.x;       // = bc*SS + s
    const int s    = bid % SS;
    const int bc   = bid / SS;

    // ---- phase 0: load cutoffs, zero hist+counts ----
    if (tid < NBC) cut[tid] = cuts[tid];
    for (int i = tid; i < FP*HIST_P + FP*NB; i += THREADS) sm[OFF_HIST + i] = 0.0f;
    __syncthreads();

    const float c0       = cut[0];
    const float inv_step = (float)NB / (cut[NB] - c0);

    // ---- phase 1: compute bins for this block's 30 pha rows ----
    // warp w handles p=w; exact searchsorted(side='left') semantics:
    // cnt = #{j : cut[j] < x}; bin = clamp(cnt-1, 0, NB-1).
    {
        const int p = wid;
        const float4* prow = (const float4*)(pha + (((long)bc*FP + p)*SS + s)*(long)TT);
        unsigned* brow = binsU + p*(TT/4);
        #pragma unroll
        for (int it = 0; it < TT/128; ++it) {
            int tq = it*32 + lane;            // float4 index within row
            float4 v = prow[tq];
            float xs[4] = {v.x, v.y, v.z, v.w};
            unsigned packed = 0;
            #pragma unroll
            for (int j = 0; j < 4; ++j) {
                float x = xs[j];
                int g = (int)floorf((x - c0) * inv_step) + 1;  // approx cnt
                g = min(max(g, 0), NBC);
                // exact correction against actual cutoffs (safe indexed reads)
                { float cl = cut[max(g-1,0)]; if (g > 0   && cl >= x) g--; }
                { float cl = cut[max(g-1,0)]; if (g > 0   && cl >= x) g--; }
                { float ch = cut[min(g,NBC-1)]; if (g < NBC && ch <  x) g++; }
                { float ch = cut[min(g,NBC-1)]; if (g < NBC && ch <  x) g++; }
                int bin = min(max(g - 1, 0), NB - 1);
                packed |= (unsigned)bin << (8*j);
            }
            brow[tq] = packed;
        }
    }
    __syncthreads();

    // ---- phase 2: scatter-sum amplitudes into per-(p,a) histograms ----
    const float* ampBase = amp + (((long)bc*FA)*SS + s)*(long)TT;  // + a*SS*TT + t
    float*          histp = hist + wid*HIST_P;
    const unsigned* brow  = binsU + wid*(TT/4);
    int  cntreg = 0;
    const int  a0   = lane;
    const int  a1   = lane + 32;
    const bool act1 = (lane < (FA - 32));   // 18 active lanes in half 1

    for (int tile = 0; tile < TT/TILE_T; ++tile) {
        const int t0 = tile * TILE_T;
        // stage amp[:, t0:t0+TILE_T] transposed -> amp_s[tloc][a] (coalesced LDG.128)
        for (int idx = tid; idx < FA * (TILE_T/4); idx += THREADS) {
            int a = idx / (TILE_T/4);
            int j = idx % (TILE_T/4);
            float4 v = *(const float4*)(ampBase + (long)a*SS*TT + t0 + j*4);
            int tl = j*4;
            amp_s[(tl+0)*FA + a] = v.x;
            amp_s[(tl+1)*FA + a] = v.y;
            amp_s[(tl+2)*FA + a] = v.z;
            amp_s[(tl+3)*FA + a] = v.w;
        }
        __syncthreads();

        // warp w scatters for p=w; bin is warp-uniform per t -> conflict-free RMW
        #pragma unroll 4
        for (int tq = 0; tq < TILE_T/4; ++tq) {
            unsigned b4 = brow[(t0 >> 2) + tq];
            #pragma unroll
            for (int j = 0; j < 4; ++j) {
                int bin = (b4 >> (8*j)) & 0xFF;
                cntreg += (bin == lane);          // lanes 0..17 collect counts
                int tl = tq*4 + j;
                float v0 = amp_s[tl*FA + a0];
                histp[a0*HIST_STRIDE + bin] += v0;
                if (act1) {
                    float v1 = amp_s[tl*FA + a1];
                    histp[a1*HIST_STRIDE + bin] += v1;
                }
            }
        }
        __syncthreads();
    }
    if (lane < NB) cnts[wid*NB + lane] = (float)cntreg;
    __syncthreads();

    // ---- phase 3: per-(p,a) entropy -> MI(s), write to scratch ----
    const float eps = 1e-9f;
    const float LN18 = 2.8903717578961645f;      // log(18) == log(18+1e-9) in fp32
    for (int task = tid; task < FP*FA; task += THREADS) {
        int p = task / FA;
        int a = task - p*FA;
        const float* h = hist + p*HIST_P + a*HIST_STRIDE;
        const float* c = cnts + p*NB;
        float m[NB];
        float msum = 0.0f;
        #pragma unroll
        for (int k = 0; k < NB; ++k) {
            m[k] = h[k] / (c[k] + eps);
            msum += m[k];
        }
        float inv = 1.0f / (msum + eps);
        float ent = 0.0f;
        #pragma unroll
        for (int k = 0; k < NB; ++k) {
            float pr = m[k] * inv;
            ent += pr * logf(pr + eps);
        }
        float mi = (LN18 + ent) * (1.0f / LN18);
        g_scratch[(long)s * NOUT + (bc*FP + p)*FA + a] = mi;
    }
}

__global__ void mi_reduce(float* __restrict__ out)
{
    int i = blockIdx.x * blockDim.x + threadIdx.x;
    if (i >= NOUT) return;
    float acc = 0.0f;
    #pragma unroll
    for (int s = 0; s < SS; ++s) acc += g_scratch[(long)s * NOUT + i];
    out[i] = acc * (1.0f / (float)SS);
}

extern "C" void kernel_launch(void* const* d_in, const int* in_sizes, int n_in,
                              void* d_out, int out_size)
{
    const float* pha  = (const float*)d_in[0];
    const float* amp  = (const float*)d_in[1];
    const float* cuts = (const float*)d_in[2];
    float* out = (float*)d_out;

    const size_t smem = SMEM_FLOATS * sizeof(float);   // 172560 B
    cudaFuncSetAttribute(mi_main, cudaFuncAttributeMaxDynamicSharedMemorySize, (int)smem);

    mi_main<<<BB*CC*SS, THREADS, smem>>>(pha, amp, cuts);
    mi_reduce<<<(NOUT + 255)/256, 256>>>(out);
}

// round 2
// speedup vs baseline: 1.2388x; 1.2388x over previous
#include <cuda_runtime.h>
#include <math.h>

// Problem shape (fixed by dataset)
#define BB 2
#define CC 16
#define FP 30
#define FA 50
#define SS 20
#define TT 1024
#define NB 18
#define NBC 19
#define NT 8            // t tiles per row
#define TILE_T 128
#define THREADS 960     // 30 warps; warp w owns p=w
#define PKA (FP*FA)     // 1500
#define NOUT (BB*CC*PKA)

// ---- dynamic SMEM byte layout ----
#define OFF_HIST   0                          // float[FP][NB][FA]  = 108000 B
#define OFF_AMP    (OFF_HIST + FP*NB*FA*4)    // float[TILE_T][FA]  =  25600 B
#define OFF_CTOT   (OFF_AMP + TILE_T*FA*4)    // float[FP][NB]      =   2160 B
#define OFF_CUT    (OFF_CTOT + FP*NB*4)       // float[20]          =     80 B
#define OFF_CNTS   (OFF_CUT + 80)             // u8[FP][NT][NB]     =   4320 -> pad 4352
#define OFF_SORT   (OFF_CNTS + 4352)          // u8[FP][NT][128]    =  30720 B
#define OFF_FLAG   (OFF_SORT + FP*NT*TILE_T)  // int
#define SMEM_BYTES (OFF_FLAG + 16)            // ~170928 B

__device__ float    g_scratch[BB*CC*SS*PKA];  // per-(bc,s) MI values
__device__ unsigned g_tick[BB*CC];            // arrival tickets (net-zero per replay)

__device__ __forceinline__ int bin_of(float x, const float* __restrict__ cut,
                                      float c0, float inv_step)
{
    // exact searchsorted(side='left'): cnt = #{j: cut[j] < x}; bin = clamp(cnt-1,0,NB-1)
    int g = (int)floorf((x - c0) * inv_step) + 1;
    g = min(max(g, 0), NBC);
    { float cl = cut[max(g-1,0)];   if (g > 0   && cl >= x) g--; }
    { float cl = cut[max(g-1,0)];   if (g > 0   && cl >= x) g--; }
    { float ch = cut[min(g,NBC-1)]; if (g < NBC && ch <  x) g++; }
    { float ch = cut[min(g,NBC-1)]; if (g < NBC && ch <  x) g++; }
    return min(max(g - 1, 0), NB - 1);
}

__global__ __launch_bounds__(THREADS, 1)
void mi_main(const float* __restrict__ pha,
             const float* __restrict__ amp,
             const float* __restrict__ cuts,
             float* __restrict__ out)
{
    extern __shared__ char smraw[];
    float*          hist    = (float*)(smraw + OFF_HIST);   // [FP][NB][FA]
    float*          amp_s   = (float*)(smraw + OFF_AMP);    // [TILE_T][FA]
    float*          cnt_tot = (float*)(smraw + OFF_CTOT);   // [FP][NB]
    float*          cut     = (float*)(smraw + OFF_CUT);    // [NBC]
    unsigned char*  cnts    = (unsigned char*)(smraw + OFF_CNTS); // [FP][NT][NB]
    unsigned char*  sorted  = (unsigned char*)(smraw + OFF_SORT); // [FP][NT][128]
    int*            sflag   = (int*)(smraw + OFF_FLAG);

    const int tid  = threadIdx.x;
    const int wid  = tid >> 5;          // = p
    const int lane = tid & 31;
    const int bid  = blockIdx.x;        // bc*SS + s
    const int s    = bid % SS;
    const int bc   = bid / SS;
    const unsigned FULL = 0xFFFFFFFFu;

    // ---- phase 0: cutoffs + zero hist ----
    if (tid < NBC) cut[tid] = cuts[tid];
    for (int i = tid; i < FP*NB*FA; i += THREADS) hist[i] = 0.0f;
    __syncthreads();

    const float c0       = cut[0];
    const float inv_step = (float)NB / (cut[NB] - c0);

    // ---- phase 1: per-(p, tile) bin + counting sort (warp w handles p=w) ----
    {
        const int p = wid;
        const float4* prow = (const float4*)(pha + (((size_t)bc*FP + p)*SS + s)*(size_t)TT);
        int ctot = 0;  // lane k (<NB): running count of bin k across tiles

        #pragma unroll
        for (int it = 0; it < NT; ++it) {
            float4 v = prow[it*32 + lane];       // items: t = it*128 + lane*4 + j
            int b[4];
            b[0] = bin_of(v.x, cut, c0, inv_step);
            b[1] = bin_of(v.y, cut, c0, inv_step);
            b[2] = bin_of(v.z, cut, c0, inv_step);
            b[3] = bin_of(v.w, cut, c0, inv_step);

            // pack per-lane per-bin counts: 3 u64, 8 bins x 8 bits each
            unsigned long long pc0 = 0, pc1 = 0, pc2 = 0;
            #pragma unroll
            for (int j = 0; j < 4; ++j) {
                int w = b[j] >> 3, sh = (b[j] & 7) * 8;
                unsigned long long one = 1ULL << sh;
                if (w == 0) pc0 += one; else if (w == 1) pc1 += one; else pc2 += one;
            }
            // inclusive scan over lanes
            unsigned long long in0 = pc0, in1 = pc1, in2 = pc2;
            #pragma unroll
            for (int d = 1; d < 32; d <<= 1) {
                unsigned long long n0 = __shfl_up_sync(FULL, in0, d);
                unsigned long long n1 = __shfl_up_sync(FULL, in1, d);
                unsigned long long n2 = __shfl_up_sync(FULL, in2, d);
                if (lane >= d) { in0 += n0; in1 += n1; in2 += n2; }
            }
            unsigned long long ex0 = in0 - pc0, ex1 = in1 - pc1, ex2 = in2 - pc2;

            // totals (lane 31 inclusive) broadcast
            unsigned long long t0 = __shfl_sync(FULL, in0, 31);
            unsigned long long t1 = __shfl_sync(FULL, in1, 31);
            unsigned long long t2 = __shfl_sync(FULL, in2, 31);

            int myTot = 0;
            if (lane < NB) {
                int w = lane >> 3, sh = (lane & 7) * 8;
                unsigned long long tw = (w == 0) ? t0 : (w == 1) ? t1 : t2;
                myTot = (int)((tw >> sh) & 0xFF);
            }
            // exclusive scan over lanes of per-bin totals -> base offsets
            int ib = myTot;
            #pragma unroll
            for (int d = 1; d < 32; d <<= 1) {
                int n = __shfl_up_sync(FULL, ib, d);
                if (lane >= d) ib += n;
            }
            int base_k = ib - myTot;   // valid for lane < NB

            if (lane < NB) {
                cnts[(p*NT + it)*NB + lane] = (unsigned char)myTot;
                ctot += myTot;
            }

            // scatter: pos = base[b] + (#same-bin items in earlier lanes) + (#earlier own slots)
            unsigned char* so = sorted + (p*NT + it)*TILE_T;
            #pragma unroll
            for (int j = 0; j < 4; ++j) {
                int bb = b[j];
                int w  = bb >> 3, n = bb & 7;
                unsigned long long ew = (w == 0) ? ex0 : (w == 1) ? ex1 : ex2;
                int cross = (int)((ew >> (n*8)) & 0xFF);
                int own = 0;
                #pragma unroll
                for (int j2 = 0; j2 < 4; ++j2)
                    if (j2 < j) own += (b[j2] == bb);
                int bs  = __shfl_sync(FULL, base_k, bb);
                int pos = bs + cross + own;
                so[pos] = (unsigned char)(lane*4 + j);
            }
        }
        if (lane < NB) cnt_tot[p*NB + lane] = (float)ctot;
    }
    __syncthreads();

    // ---- phase 2: bin-sorted gather-accumulate ----
    const float* ampBase = amp + (((size_t)bc*FA)*SS + s)*(size_t)TT; // + a*SS*TT + t
    const int p   = wid;
    const int a0  = 2*lane;
    const bool act = (a0 < FA);            // lanes 0..24
    const int aL  = act ? a0 : (FA - 2);   // clamp to stay in-bounds

    for (int it = 0; it < NT; ++it) {
        const int t0 = it * TILE_T;
        // stage amp[:, t0:t0+128] transposed -> amp_s[tl][a] (coalesced LDG.128)
        for (int idx = tid; idx < FA*(TILE_T/4); idx += THREADS) {
            int a = idx >> 5, j = idx & 31;
            float4 v = *(const float4*)(ampBase + (size_t)a*SS*TT + t0 + j*4);
            int tl = j*4;
            amp_s[(tl+0)*FA + a] = v.x;
            amp_s[(tl+1)*FA + a] = v.y;
            amp_s[(tl+2)*FA + a] = v.z;
            amp_s[(tl+3)*FA + a] = v.w;
        }
        __syncthreads();

        const unsigned char* so = sorted + (p*NT + it)*TILE_T;
        const unsigned char* cc = cnts   + (p*NT + it)*NB;
        int pos = 0;
        for (int k = 0; k < NB; ++k) {
            int c = cc[k];                  // warp-uniform
            float ax = 0.0f, ay = 0.0f;
            int i = 0;
            for (; i + 1 < c; i += 2) {
                int u1 = so[pos + i], u2 = so[pos + i + 1];
                float2 v1 = *(const float2*)&amp_s[u1*FA + aL];
                float2 v2 = *(const float2*)&amp_s[u2*FA + aL];
                ax += v1.x; ay += v1.y;
                ax += v2.x; ay += v2.y;
            }
            if (i < c) {
                int u1 = so[pos + i];
                float2 v1 = *(const float2*)&amp_s[u1*FA + aL];
                ax += v1.x; ay += v1.y;
            }
            pos += c;
            if (act) {
                float2* h = (float2*)&hist[(p*NB + k)*FA + a0];
                float2 hv = *h; hv.x += ax; hv.y += ay; *h = hv;
            }
        }
        __syncthreads();
    }

    // ---- phase 3: entropy -> MI per (p,a), write scratch ----
    const float eps  = 1e-9f;
    const float LN18 = 2.8903717578961645f;
    for (int task = tid; task < PKA; task += THREADS) {
        int pp = task / FA;
        int aa = task - pp*FA;
        float m[NB];
        float msum = 0.0f;
        #pragma unroll
        for (int k = 0; k < NB; ++k) {
            m[k] = hist[(pp*NB + k)*FA + aa] / (cnt_tot[pp*NB + k] + eps);
            msum += m[k];
        }
        float inv = 1.0f / (msum + eps);
        float ent = 0.0f;
        #pragma unroll
        for (int k = 0; k < NB; ++k) {
            float pr = m[k] * inv;
            ent += pr * logf(pr + eps);
        }
        g_scratch[((size_t)bc*SS + s)*PKA + task] = (LN18 + ent) * (1.0f / LN18);
    }

    // ---- phase 4: last block per bc reduces over s ----
    __threadfence();
    __syncthreads();
    if (tid == 0) {
        unsigned old = atomicAdd(&g_tick[bc], 1u);
        *sflag = (old == SS - 1) ? 1 : 0;
    }
    __syncthreads();
    if (*sflag) {
        __threadfence();   // acquire: see all 20 blocks' scratch
        for (int i = tid; i < PKA; i += THREADS) {
            float acc = 0.0f;
            #pragma unroll
            for (int ss2 = 0; ss2 < SS; ++ss2)
                acc += g_scratch[((size_t)bc*SS + ss2)*PKA + i];
            out[(size_t)bc*PKA + i] = acc * (1.0f / (float)SS);
        }
        __syncthreads();
        if (tid == 0) g_tick[bc] = 0;   // net-zero for next replay
    }
}

extern "C" void kernel_launch(void* const* d_in, const int* in_sizes, int n_in,
                              void* d_out, int out_size)
{
    const float* pha  = (const float*)d_in[0];
    const float* amp  = (const float*)d_in[1];
    const float* cuts = (const float*)d_in[2];
    float* out = (float*)d_out;

    cudaFuncSetAttribute(mi_main, cudaFuncAttributeMaxDynamicSharedMemorySize, SMEM_BYTES);
    mi_main<<<BB*CC*SS, THREADS, SMEM_BYTES>>>(pha, amp, cuts, out);
}